// round 15
// baseline (speedup 1.0000x reference)
#include <cuda_runtime.h>
#include <cuda_bf16.h>
#include <cstdint>
#include <limits.h>

#define NPTS 4096
#define DIM  768
#define WD   64
#define KTOP 100
#define NT   528
#define TAU  0.05f

// dynamic smem layout (bytes)
#define OFF_FA  0               // fp32 A rows 0-63:  [2][16][68]  = 8704
#define OFF_FB  8704            // fp32 B cols 0-127: [2][16][132] = 16896
#define OFF_HAH 25600           // bf16 hi A rows 64-127: [2][64][24] = 6144
#define OFF_HAL 31744
#define OFF_HBH 37888           // bf16 hi B cols 0-127:  [2][128][24] = 12288
#define OFF_HBL 50176
#define SMEM_DYN 62464
#define FA_BUF 1088             // floats per buffer (16*68)
#define FB_BUF 2112             // (16*132)
#define HA_BUF 3072             // bytes (64*24*2)
#define HB_BUF 6144             // bytes (128*24*2)

// scratch (no allocations allowed)
__device__ int            g_counts[NPTS];
__device__ int            g_best;
__device__ int            g_q;
__device__ float          g_simseed[NPTS];
__device__ int            g_s[NPTS];
__device__ __nv_bfloat16  g_Xh[NPTS * DIM];
__device__ __nv_bfloat16  g_Xl[NPTS * DIM];

// ---------------------------------------------------------------------------
__device__ __forceinline__ void ldsm_x4(uint32_t r[4], uint32_t addr) {
    asm volatile("ldmatrix.sync.aligned.m8n8.x4.shared.b16 {%0,%1,%2,%3}, [%4];"
                 : "=r"(r[0]), "=r"(r[1]), "=r"(r[2]), "=r"(r[3]) : "r"(addr));
}
__device__ __forceinline__ void mma_bf16(float d[4], const uint32_t a[4],
                                         uint32_t b0, uint32_t b1) {
    asm volatile("mma.sync.aligned.m16n8k16.row.col.f32.bf16.bf16.f32 "
                 "{%0,%1,%2,%3},{%4,%5,%6,%7},{%8,%9},{%0,%1,%2,%3};"
                 : "+f"(d[0]), "+f"(d[1]), "+f"(d[2]), "+f"(d[3])
                 : "r"(a[0]), "r"(a[1]), "r"(a[2]), "r"(a[3]), "r"(b0), "r"(b1));
}
__device__ __forceinline__ float exact_dot(const float* __restrict__ X, int gi, int gj) {
    const float4* a = (const float4*)(X + (size_t)gi * DIM);
    const float4* b = (const float4*)(X + (size_t)gj * DIM);
    float s = 0.0f;
    #pragma unroll 4
    for (int d = 0; d < DIM / 4; d++) {
        float4 u = a[d], w = b[d];
        s += u.x * w.x + u.y * w.y + u.z * w.z + u.w * w.w;
    }
    return s;
}
__device__ __forceinline__ void decode_tile(int t, int& bi, int& bj) {
    bi = (int)((65.0 - sqrt(4225.0 - 8.0 * (double)t)) * 0.5);
    while (bi * (65 - bi) / 2 > t) bi--;
    while ((bi + 1) * (64 - bi) / 2 <= t) bi++;
    bj = bi + (t - bi * (65 - bi) / 2);
}
__device__ __forceinline__ int blend_seed(int key, const int* __restrict__ attn) {
    int idx = key & 4095;
    int r = idx >> 6, c = idx & 63;
    int tr = r + attn[0];
    int tc = c + attn[1];
    int rr = tr >> 1; if (tr & 1) rr += (rr & 1);
    int cc = tc >> 1; if (tc & 1) cc += (cc & 1);
    return rr * WD + cc;
}

// ---------------------------------------------------------------------------
// 0) fp32 -> (bf16 hi, lo) split + global init
// ---------------------------------------------------------------------------
__global__ void convert_split(const float* __restrict__ X) {
    int i = blockIdx.x * blockDim.x + threadIdx.x;
    if (i < NPTS) g_counts[i] = 1;
    if (i == 0) { g_best = INT_MAX; g_q = 0; }
    float4 v = ((const float4*)X)[i];
    __nv_bfloat16 hx = __float2bfloat16_rn(v.x);
    __nv_bfloat16 hy = __float2bfloat16_rn(v.y);
    __nv_bfloat16 hz = __float2bfloat16_rn(v.z);
    __nv_bfloat16 hw = __float2bfloat16_rn(v.w);
    __nv_bfloat162* oh = (__nv_bfloat162*)g_Xh;
    __nv_bfloat162* ol = (__nv_bfloat162*)g_Xl;
    oh[2 * i + 0] = __nv_bfloat162(hx, hy);
    oh[2 * i + 1] = __nv_bfloat162(hz, hw);
    ol[2 * i + 0] = __floats2bfloat162_rn(v.x - __bfloat162float(hx),
                                          v.y - __bfloat162float(hy));
    ol[2 * i + 1] = __floats2bfloat162_rn(v.z - __bfloat162float(hz),
                                          v.w - __bfloat162float(hw));
}

// ---------------------------------------------------------------------------
// 1) split-tile dual-pipe GEMM: one CTA per SM; warps 0-3 = FFMA2 on rows
//    0-63 (fma pipe), warps 4-7 = 3-pass bf16 HMMA on rows 64-127 (tensor
//    pipe). Shared 128-col B staged in fp32 AND bf16 hi/lo. Queue-fed.
// ---------------------------------------------------------------------------
__global__ __launch_bounds__(256)
void split_gemm(const float* __restrict__ X) {
    extern __shared__ char sm[];
    __shared__ int rowSum[128], colSum[128], qs;
    float* FA = (float*)(sm + OFF_FA);
    float* FB = (float*)(sm + OFF_FB);
    uint32_t smadr = (uint32_t)__cvta_generic_to_shared(sm);

    int tid = threadIdx.x;
    bool isF = (tid < 128);
    int lane = tid & 31;

    // FFMA2 indices
    int tx = tid & 15, ty = (tid >> 4) & 7;   // 16x8 grid over 128 cols x 64 rows
    // HMMA indices
    int hw = (tid - 128) >> 5;                // warp 0-3 -> rows 64+16w..+15
    int htid = tid - 128;

    // HMMA ldsm lane addressing (tile-independent)
    uint32_t aHb = smadr + OFF_HAH + (uint32_t)(((hw * 16 + (lane & 15)) * 24 + (lane >> 4) * 8) * 2);
    uint32_t aLb = aHb + (OFF_HAL - OFF_HAH);
    int grp = lane >> 3;
    int nB  = ((grp >> 1) * 8) + (lane & 7);
    int koB = (grp & 1) * 8;
    uint32_t bHb = smadr + OFF_HBH + (uint32_t)((nB * 24 + koB) * 2);
    uint32_t bLb = bHb + (OFF_HBL - OFF_HBH);

    while (true) {
        if (tid == 0) qs = atomicAdd(&g_q, 1);
        __syncthreads();
        int t = qs;
        if (t >= NT) return;
        int bi, bj; decode_tile(t, bi, bj);
        int i0 = bi * 128, j0 = bj * 128;
        bool diag = (bi == bj);

        if (isF) {
            // ---------------- FFMA2 half: rows i0..i0+63 ----------------
            unsigned long long acc2[4][8];
            #pragma unroll
            for (int p = 0; p < 4; p++)
                #pragma unroll
                for (int n = 0; n < 8; n++) acc2[p][n] = 0ull;

            const float4* lB = (const float4*)(X + (size_t)(j0 + tid) * DIM);
            const float4* lA = (tid < 64)
                ? (const float4*)(X + (size_t)(i0 + tid) * DIM) : (const float4*)0;
            float4 rb[4], ra[4];

#define F_LDG(kt) { _Pragma("unroll") for (int q = 0; q < 4; q++) { \
                rb[q] = lB[(kt) * 4 + q]; \
                if (lA) ra[q] = lA[(kt) * 4 + q]; } }
#define F_STS(buf) { _Pragma("unroll") for (int q = 0; q < 4; q++) \
                _Pragma("unroll") for (int e = 0; e < 4; e++) { \
                FB[(buf) * FB_BUF + (q * 4 + e) * 132 + tid] = (&rb[q].x)[e]; \
                if (lA) FA[(buf) * FA_BUF + (q * 4 + e) * 68 + tid] = (&ra[q].x)[e]; } }

            F_LDG(0); F_STS(0);
            __syncthreads();

            for (int kt = 0; kt < 48; kt++) {
                int buf = kt & 1;
                if (kt + 1 < 48) F_LDG(kt + 1);

                #pragma unroll
                for (int k = 0; k < 16; k++) {
                    const float* arow = FA + (buf * 16 + k) * 68;
                    const float* brow = FB + (buf * 16 + k) * 132;
                    const ulonglong2* ap = (const ulonglong2*)(arow + ty * 8);
                    ulonglong2 a01 = ap[0], a23 = ap[1];
                    unsigned long long av[4] = {a01.x, a01.y, a23.x, a23.y};
                    const float4* bp = (const float4*)(brow + tx * 8);
                    float4 b0 = bp[0], b1 = bp[1];
                    float bf[8] = {b0.x, b0.y, b0.z, b0.w, b1.x, b1.y, b1.z, b1.w};
                    unsigned long long b2[8];
                    #pragma unroll
                    for (int n = 0; n < 8; n++)
                        asm("mov.b64 %0, {%1, %2};" : "=l"(b2[n]) : "f"(bf[n]), "f"(bf[n]));
                    #pragma unroll
                    for (int p = 0; p < 4; p++)
                        #pragma unroll
                        for (int n = 0; n < 8; n++)
                            asm("fma.rn.f32x2 %0, %1, %2, %0;"
                                : "+l"(acc2[p][n]) : "l"(av[p]), "l"(b2[n]));
                }

                if (kt + 1 < 48) F_STS(buf ^ 1);
                __syncthreads();
            }
#undef F_LDG
#undef F_STS

            rowSum[tid] = 0; colSum[tid] = 0;
            __syncthreads();

            int rcnt[8], ccnt[8];
            #pragma unroll
            for (int m = 0; m < 8; m++) { rcnt[m] = 0; ccnt[m] = 0; }
            #pragma unroll
            for (int p = 0; p < 4; p++) {
                #pragma unroll
                for (int n = 0; n < 8; n++) {
                    unsigned long long a = acc2[p][n];
                    float vlo = __uint_as_float((unsigned)(a & 0xffffffffull));
                    float vhi = __uint_as_float((unsigned)(a >> 32));
                    int gj = j0 + tx * 8 + n;
                    int gilo = i0 + ty * 8 + 2 * p;
                    int clo = (vlo >= 0.0f) && (!diag || gj > gilo);
                    int chi = (vhi >= 0.0f) && (!diag || gj > gilo + 1);
                    rcnt[2 * p] += clo; rcnt[2 * p + 1] += chi;
                    ccnt[n] += clo + chi;
                }
            }
            #pragma unroll
            for (int m = 0; m < 8; m++) atomicAdd(&rowSum[ty * 8 + m], rcnt[m]);
            #pragma unroll
            for (int n = 0; n < 8; n++) atomicAdd(&colSum[tx * 8 + n], ccnt[n]);
            __syncthreads();

            atomicAdd(&g_counts[i0 + tid], rowSum[tid]);
            atomicAdd(&g_counts[j0 + tid], colSum[tid]);
        } else {
            // ---------------- HMMA half: rows i0+64..i0+127 ----------------
            float acc[16][4];
            #pragma unroll
            for (int jn = 0; jn < 16; jn++)
                #pragma unroll
                for (int e = 0; e < 4; e++) acc[jn][e] = 0.0f;

            const uint4* lBh = (const uint4*)(g_Xh + (size_t)(j0 + htid) * DIM);
            const uint4* lBl = (const uint4*)(g_Xl + (size_t)(j0 + htid) * DIM);
            const uint4* lAh = (htid < 64)
                ? (const uint4*)(g_Xh + (size_t)(i0 + 64 + htid) * DIM) : (const uint4*)0;
            const uint4* lAl = (htid < 64)
                ? (const uint4*)(g_Xl + (size_t)(i0 + 64 + htid) * DIM) : (const uint4*)0;
            uint4 pbh[2], pbl[2], pah[2], pal[2];

#define H_LDG(kt) { _Pragma("unroll") for (int h = 0; h < 2; h++) { \
                pbh[h] = lBh[(kt) * 2 + h]; pbl[h] = lBl[(kt) * 2 + h]; \
                if (lAh) { pah[h] = lAh[(kt) * 2 + h]; pal[h] = lAl[(kt) * 2 + h]; } } }
#define H_STS(buf) { _Pragma("unroll") for (int h = 0; h < 2; h++) { \
                *(uint4*)(sm + OFF_HBH + (buf) * HB_BUF + htid * 48 + h * 16) = pbh[h]; \
                *(uint4*)(sm + OFF_HBL + (buf) * HB_BUF + htid * 48 + h * 16) = pbl[h]; \
                if (lAh) { \
                *(uint4*)(sm + OFF_HAH + (buf) * HA_BUF + htid * 48 + h * 16) = pah[h]; \
                *(uint4*)(sm + OFF_HAL + (buf) * HA_BUF + htid * 48 + h * 16) = pal[h]; } } }

            H_LDG(0); H_STS(0);
            __syncthreads();

            for (int kt = 0; kt < 48; kt++) {
                int buf = kt & 1;
                if (kt + 1 < 48) H_LDG(kt + 1);

                uint32_t ah[4], al[4];
                ldsm_x4(ah, aHb + buf * HA_BUF);
                ldsm_x4(al, aLb + buf * HA_BUF);
                #pragma unroll
                for (int jb = 0; jb < 8; jb++) {
                    uint32_t bh[4], bl[4];
                    ldsm_x4(bh, bHb + buf * HB_BUF + jb * 768);
                    ldsm_x4(bl, bLb + buf * HB_BUF + jb * 768);
                    #pragma unroll
                    for (int jh = 0; jh < 2; jh++) {
                        int o = jh * 2;
                        float* d = acc[jb * 2 + jh];
                        mma_bf16(d, ah, bh[o], bh[o + 1]);
                        mma_bf16(d, ah, bl[o], bl[o + 1]);
                        mma_bf16(d, al, bh[o], bh[o + 1]);
                    }
                }

                if (kt + 1 < 48) H_STS(buf ^ 1);
                __syncthreads();
            }
#undef H_LDG
#undef H_STS

            __syncthreads();   // pairs with FFMA2 group's rowSum-zero sync

            int rb = 64 + hw * 16 + (lane >> 2);
            int cb = (lane & 3) * 2;
            int rc[2] = {0, 0};
            int cc[32];
            #pragma unroll
            for (int q = 0; q < 32; q++) cc[q] = 0;
            #pragma unroll
            for (int jn = 0; jn < 16; jn++) {
                #pragma unroll
                for (int e4 = 0; e4 < 4; e4++) {
                    int h8 = e4 >> 1, e = e4 & 1;
                    int gi = i0 + rb + h8 * 8;
                    int gj = j0 + jn * 8 + cb + e;
                    if (diag && gj <= gi) continue;
                    float v = acc[jn][e4];
                    int bit;
                    if (fabsf(v) >= TAU) bit = (v >= 0.0f);
                    else                 bit = (exact_dot(X, gi, gj) >= 0.0f);
                    rc[h8] += bit;
                    cc[jn * 2 + e] += bit;
                }
            }
            #pragma unroll
            for (int h8 = 0; h8 < 2; h8++) atomicAdd(&rowSum[rb + h8 * 8], rc[h8]);
            #pragma unroll
            for (int jn = 0; jn < 16; jn++)
                #pragma unroll
                for (int e = 0; e < 2; e++)
                    atomicAdd(&colSum[jn * 8 + cb + e], cc[jn * 2 + e]);
            __syncthreads();
            // g_counts flush handled by FFMA2 threads (tid<128)
        }
    }
}

// ---------------------------------------------------------------------------
// 2) grid-wide argmin of counts via packed key atomicMin
// ---------------------------------------------------------------------------
__global__ void argmin_kernel() {
    int i = blockIdx.x * blockDim.x + threadIdx.x;
    int key = g_counts[i] * 4096 + i;
    #pragma unroll
    for (int o = 16; o > 0; o >>= 1)
        key = min(key, __shfl_xor_sync(0xffffffffu, key, o));
    if ((threadIdx.x & 31) == 0) atomicMin(&g_best, key);
}

// ---------------------------------------------------------------------------
// 3) sim[seed][j] + initial mask
// ---------------------------------------------------------------------------
__global__ void seedrow_kernel(const float* __restrict__ X,
                               const int* __restrict__ attn) {
    int gwarp = (blockIdx.x * blockDim.x + threadIdx.x) >> 5;
    int lane  = threadIdx.x & 31;
    if (gwarp >= NPTS) return;
    int seed = blend_seed(g_best, attn);
    const float4* xs = (const float4*)(X + (size_t)seed * DIM);
    const float4* xj = (const float4*)(X + (size_t)gwarp * DIM);
    float p = 0.0f;
    #pragma unroll
    for (int q = 0; q < 6; q++) {
        float4 u = xs[lane + 32 * q], w = xj[lane + 32 * q];
        p += u.x * w.x + u.y * w.y + u.z * w.z + u.w * w.w;
    }
    #pragma unroll
    for (int o = 16; o > 0; o >>= 1) p += __shfl_down_sync(0xffffffffu, p, o);
    if (lane == 0) {
        g_simseed[gwarp] = p;
        g_s[gwarp] = (p >= 0.0f) ? 1 : 0;
    }
}

// ---------------------------------------------------------------------------
// 4) top-100 via bitonic sort on packed 64-bit keys
// ---------------------------------------------------------------------------
__device__ __forceinline__ unsigned ford(float v) {
    unsigned u = __float_as_uint(v);
    return (u & 0x80000000u) ? ~u : (u | 0x80000000u);
}
__global__ void topk_kernel(const int* __restrict__ attn) {
    __shared__ unsigned long long sk[NPTS];
    int tid = threadIdx.x;
    int seed = blend_seed(g_best, attn);
    for (int i = tid; i < NPTS; i += 1024)
        sk[i] = ((unsigned long long)ford(g_simseed[i]) << 32)
              | (unsigned)(NPTS - 1 - i);
    __syncthreads();
    for (int k = 2; k <= NPTS; k <<= 1) {
        for (int j = k >> 1; j > 0; j >>= 1) {
            for (int i = tid; i < NPTS; i += 1024) {
                int ixj = i ^ j;
                if (ixj > i) {
                    unsigned long long k1 = sk[i], k2 = sk[ixj];
                    bool g = (k1 < k2);
                    bool dirDesc = ((i & k) == 0);
                    if (g == dirDesc) { sk[i] = k2; sk[ixj] = k1; }
                }
            }
            __syncthreads();
        }
    }
    unsigned long long k99 = sk[KTOP - 1];
    for (int i = tid; i < NPTS; i += 1024) {
        int s = g_s[i];
        if (i == seed) s = 1;
        unsigned long long ki = ((unsigned long long)ford(g_simseed[i]) << 32)
                              | (unsigned)(NPTS - 1 - i);
        g_s[i] = (ki >= k99) ? s : 0;
    }
}

// ---------------------------------------------------------------------------
// 5) sequential expansion, single warp
// ---------------------------------------------------------------------------
__global__ void scan_kernel(const float* __restrict__ X) {
    __shared__ int list[KTOP + 32];
    int lane = threadIdx.x;

    int cnt = 0;
    for (int c = 0; c < NPTS / 32; c++) {
        int idx = c * 32 + lane;
        int val = g_s[idx];
        unsigned m = __ballot_sync(0xffffffffu, val != 0);
        if (val) {
            int pos = cnt + __popc(m & ((1u << lane) - 1));
            if (pos < KTOP + 32) list[pos] = idx;
        }
        cnt += __popc(m);
    }
    int na = (cnt < KTOP + 32) ? cnt : (KTOP + 32);
    __syncwarp();

    float4 v4[6];
    #pragma unroll
    for (int q = 0; q < 6; q++) v4[q] = make_float4(0.f, 0.f, 0.f, 0.f);
    for (int l = 0; l < na; l++) {
        const float4* x = (const float4*)(X + (size_t)list[l] * DIM);
        #pragma unroll
        for (int q = 0; q < 6; q++) {
            float4 u = x[lane + 32 * q];
            v4[q].x += u.x; v4[q].y += u.y; v4[q].z += u.z; v4[q].w += u.w;
        }
    }

    for (int l = 0; l < na; l++) {
        int i = list[l];
        const float4* x = (const float4*)(X + (size_t)i * DIM);
        float4 xr[6];
        float dot = 0.0f;
        #pragma unroll
        for (int q = 0; q < 6; q++) {
            xr[q] = x[lane + 32 * q];
            dot += xr[q].x * v4[q].x + xr[q].y * v4[q].y
                 + xr[q].z * v4[q].z + xr[q].w * v4[q].w;
        }
        #pragma unroll
        for (int o = 16; o > 0; o >>= 1) dot += __shfl_xor_sync(0xffffffffu, dot, o);
        if (dot <= 0.0f) {
            if (lane == 0) g_s[i] = 0;
            #pragma unroll
            for (int q = 0; q < 6; q++) {
                v4[q].x -= xr[q].x; v4[q].y -= xr[q].y;
                v4[q].z -= xr[q].z; v4[q].w -= xr[q].w;
            }
        }
    }
}

// ---------------------------------------------------------------------------
// 6) 8-connected components
// ---------------------------------------------------------------------------
__global__ void cc_kernel(float* __restrict__ outp) {
    __shared__ int lab[66 * 66];
    __shared__ int changed;
    const int BIG = NPTS + 1;
    int tid = threadIdx.x;

    for (int p = tid; p < 66 * 66; p += 1024) lab[p] = BIG;
    __syncthreads();

    int fgp[4], pos[4];
    #pragma unroll
    for (int q = 0; q < 4; q++) {
        int p = tid + q * 1024;
        int r = p >> 6, c = p & 63;
        pos[q] = (r + 1) * 66 + (c + 1);
        fgp[q] = g_s[p];
        lab[pos[q]] = fgp[q] ? (p + 1) : BIG;
    }
    __syncthreads();

    while (true) {
        if (tid == 0) changed = 0;
        __syncthreads();
        int lc = 0;
        #pragma unroll
        for (int q = 0; q < 4; q++) {
            if (fgp[q]) {
                int pp = pos[q];
                int m = lab[pp];
                m = min(m, lab[pp - 67]); m = min(m, lab[pp - 66]); m = min(m, lab[pp - 65]);
                m = min(m, lab[pp - 1]);                            m = min(m, lab[pp + 1]);
                m = min(m, lab[pp + 65]); m = min(m, lab[pp + 66]); m = min(m, lab[pp + 67]);
                if (m < lab[pp]) { lab[pp] = m; lc = 1; }
            }
        }
        if (lc) changed = 1;
        __syncthreads();
        int done = !changed;
        __syncthreads();
        if (done) break;
    }

    #pragma unroll
    for (int q = 0; q < 4; q++) {
        int p = tid + q * 1024;
        outp[p] = fgp[q] ? (float)lab[pos[q]] : 0.0f;
    }
}

// ---------------------------------------------------------------------------
extern "C" void kernel_launch(void* const* d_in, const int* in_sizes, int n_in,
                              void* d_out, int out_size) {
    const float* X;
    const int*   attn;
    if (n_in >= 2 && in_sizes[0] == 2) {
        attn = (const int*)d_in[0];
        X    = (const float*)d_in[1];
    } else {
        X    = (const float*)d_in[0];
        attn = (const int*)d_in[1];
    }
    float* outp = (float*)d_out;

    cudaFuncSetAttribute(split_gemm, cudaFuncAttributeMaxDynamicSharedMemorySize, SMEM_DYN);

    convert_split<<<(NPTS * DIM / 4) / 256, 256>>>(X);
    split_gemm<<<148, 256, SMEM_DYN>>>(X);
    argmin_kernel<<<16, 256>>>();
    seedrow_kernel<<<NPTS / 8, 256>>>(X, attn);
    topk_kernel<<<1, 1024>>>(attn);
    scan_kernel<<<1, 32>>>(X);
    cc_kernel<<<1, 1024>>>(outp);
}

// round 16
// speedup vs baseline: 1.0465x; 1.0465x over previous
#include <cuda_runtime.h>
#include <cuda_fp16.h>
#include <cstdint>
#include <limits.h>

#define NPTS 4096
#define DIM  768
#define WD   64
#define KTOP 100
#define NT   528
#define BM   128
#define PADK 24
#define TBA  (BM * PADK * 2)        // 6144 bytes per tile array
#define TAU  0.15f                  // 19 sigma of the fp16 2-pass residual

// scratch (no allocations allowed)
__device__ int     g_counts[NPTS];
__device__ int     g_best;          // packed argmin key: count*4096 + idx
__device__ float   g_simseed[NPTS];
__device__ int     g_s[NPTS];
__device__ __half  g_H[NPTS * DIM]; // fp16 hi (6.3MB)
__device__ __half  g_L[NPTS * DIM]; // fp16 lo (6.3MB)

// ---------------------------------------------------------------------------
__device__ __forceinline__ void ldsm_x4(uint32_t r[4], uint32_t addr) {
    asm volatile("ldmatrix.sync.aligned.m8n8.x4.shared.b16 {%0,%1,%2,%3}, [%4];"
                 : "=r"(r[0]), "=r"(r[1]), "=r"(r[2]), "=r"(r[3]) : "r"(addr));
}
__device__ __forceinline__ void mma_f16(float d[4], const uint32_t a[4],
                                        uint32_t b0, uint32_t b1) {
    asm volatile("mma.sync.aligned.m16n8k16.row.col.f32.f16.f16.f32 "
                 "{%0,%1,%2,%3},{%4,%5,%6,%7},{%8,%9},{%0,%1,%2,%3};"
                 : "+f"(d[0]), "+f"(d[1]), "+f"(d[2]), "+f"(d[3])
                 : "r"(a[0]), "r"(a[1]), "r"(a[2]), "r"(a[3]), "r"(b0), "r"(b1));
}
__device__ __forceinline__ float exact_dot(const float* __restrict__ X, int gi, int gj) {
    const float4* a = (const float4*)(X + (size_t)gi * DIM);
    const float4* b = (const float4*)(X + (size_t)gj * DIM);
    float s = 0.0f;
    #pragma unroll 4
    for (int d = 0; d < DIM / 4; d++) {
        float4 u = a[d], w = b[d];
        s += u.x * w.x + u.y * w.y + u.z * w.z + u.w * w.w;
    }
    return s;
}
__device__ __forceinline__ int blend_seed(int key, const int* __restrict__ attn) {
    int idx = key & 4095;
    int r = idx >> 6, c = idx & 63;
    int tr = r + attn[0];
    int tc = c + attn[1];
    int rr = tr >> 1; if (tr & 1) rr += (rr & 1);
    int cc = tc >> 1; if (tc & 1) cc += (cc & 1);
    return rr * WD + cc;
}

// ---------------------------------------------------------------------------
// 0) fp32 -> (fp16 hi, fp16 lo) split + global init (fused)
// ---------------------------------------------------------------------------
__global__ void convert_split(const float* __restrict__ X) {
    int i = blockIdx.x * blockDim.x + threadIdx.x;   // one float4 per thread
    if (i < NPTS) g_counts[i] = 1;                   // diagonal always >= 0
    if (i == 0) g_best = INT_MAX;
    float4 v = ((const float4*)X)[i];
    __half hx = __float2half_rn(v.x);
    __half hy = __float2half_rn(v.y);
    __half hz = __float2half_rn(v.z);
    __half hw = __float2half_rn(v.w);
    __half2* oh = (__half2*)g_H;
    __half2* ol = (__half2*)g_L;
    oh[2 * i + 0] = __half2(hx, hy);
    oh[2 * i + 1] = __half2(hz, hw);
    ol[2 * i + 0] = __floats2half2_rn(v.x - __half2float(hx),
                                      v.y - __half2float(hy));
    ol[2 * i + 1] = __floats2half2_rn(v.z - __half2float(hz),
                                      v.w - __half2float(hw));
}

// ---------------------------------------------------------------------------
// 1) triangular count-GEMM, fp16 2-pass HMMA: D = A_hi*B_hi + A_hi*B_lo
//    (= A_hi * B to ~22 bits; residual = A_lo*B, |.| < TAU triggers exact
//    fp32 repair). 128x128 tile, 8 warps (4x2), warp tile 32x64, m16n8k16,
//    double-buffered smem, ONE sync per k-step, register prefetch.
// ---------------------------------------------------------------------------
__global__ __launch_bounds__(256)
void count_mma(const float* __restrict__ X) {
    // decode triangular tile index t -> (bi, bj), bj >= bi
    int t = blockIdx.x;
    int bi = (int)((65.0 - sqrt(4225.0 - 8.0 * (double)t)) * 0.5);
    while (bi * (65 - bi) / 2 > t) bi--;
    while ((bi + 1) * (64 - bi) / 2 <= t) bi++;
    int bj = bi + (t - bi * (65 - bi) / 2);

    __shared__ __half Ah[2][BM * PADK];
    __shared__ __half Bh[2][BM * PADK];
    __shared__ __half Bl[2][BM * PADK];
    __shared__ int rowSum[BM];
    __shared__ int colSum[BM];

    int tid  = threadIdx.x;
    int warp = tid >> 5, lane = tid & 31;
    int wm = warp & 3;          // M group: rows wm*32..+31
    int wn = warp >> 2;         // N group: cols wn*64..+63
    int i0 = bi * BM, j0 = bj * BM;

    float acc[2][8][4];
    #pragma unroll
    for (int im = 0; im < 2; im++)
        #pragma unroll
        for (int jn = 0; jn < 8; jn++)
            #pragma unroll
            for (int e = 0; e < 4; e++) acc[im][jn][e] = 0.0f;

    // global load mapping: thread -> (row, 16B half) of the 128x16 stage
    int lrow = tid >> 1, lhalf = tid & 1;
    const uint4* gA = (const uint4*)(g_H + (size_t)(i0 + lrow) * DIM);
    const uint4* gBh = (const uint4*)(g_H + (size_t)(j0 + lrow) * DIM);
    const uint4* gBl = (const uint4*)(g_L + (size_t)(j0 + lrow) * DIM);
    uint32_t stoff = (uint32_t)((lrow * PADK + lhalf * 8) * 2);

    // ldmatrix source lanes
    int rowA  = lane & 15;
    int koffA = (lane >> 4) * 8;
    int grp   = lane >> 3;
    int nB    = ((grp >> 1) * 8) + (lane & 7);
    int koffB = (grp & 1) * 8;

    uint32_t aAddr[2], bAddrH[4], bAddrL[4];
    {
        uint32_t ab  = (uint32_t)__cvta_generic_to_shared(&Ah[0][0]);
        uint32_t bbh = (uint32_t)__cvta_generic_to_shared(&Bh[0][0]);
        uint32_t bbl = (uint32_t)__cvta_generic_to_shared(&Bl[0][0]);
        #pragma unroll
        for (int im = 0; im < 2; im++)
            aAddr[im] = ab + ((wm * 32 + im * 16 + rowA) * PADK + koffA) * 2;
        #pragma unroll
        for (int jb = 0; jb < 4; jb++) {
            uint32_t off = ((wn * 64 + jb * 16 + nB) * PADK + koffB) * 2;
            bAddrH[jb] = bbh + off;
            bAddrL[jb] = bbl + off;
        }
    }
    const uint32_t bufBytes = TBA;

    uint4 ra, rbh, rbl;
    ra = gA[lhalf]; rbh = gBh[lhalf]; rbl = gBl[lhalf];
    *(uint4*)((char*)&Ah[0][0] + stoff) = ra;
    *(uint4*)((char*)&Bh[0][0] + stoff) = rbh;
    *(uint4*)((char*)&Bl[0][0] + stoff) = rbl;
    __syncthreads();

    for (int kt = 0; kt < 48; kt++) {
        int b = kt & 1;
        if (kt + 1 < 48) {          // prefetch next stage into registers
            int o = (kt + 1) * 2 + lhalf;
            ra = gA[o]; rbh = gBh[o]; rbl = gBl[o];
        }

        uint32_t ah[2][4], bh[4][4], bl[4][4];
        uint32_t bo = b * bufBytes;
        #pragma unroll
        for (int im = 0; im < 2; im++) ldsm_x4(ah[im], aAddr[im] + bo);
        #pragma unroll
        for (int jb = 0; jb < 4; jb++) {
            ldsm_x4(bh[jb], bAddrH[jb] + bo);
            ldsm_x4(bl[jb], bAddrL[jb] + bo);
        }

        if (kt + 1 < 48) {          // stores to the OTHER buffer
            char* dA = (char*)&Ah[b ^ 1][0];
            char* dH = (char*)&Bh[b ^ 1][0];
            char* dL = (char*)&Bl[b ^ 1][0];
            *(uint4*)(dA + stoff) = ra;
            *(uint4*)(dH + stoff) = rbh;
            *(uint4*)(dL + stoff) = rbl;
        }

        #pragma unroll
        for (int im = 0; im < 2; im++)
            #pragma unroll
            for (int jn = 0; jn < 8; jn++) {
                int jb = jn >> 1, o = (jn & 1) * 2;
                mma_f16(acc[im][jn], ah[im], bh[jb][o], bh[jb][o + 1]);
                mma_f16(acc[im][jn], ah[im], bl[jb][o], bl[jb][o + 1]);
            }

        __syncthreads();             // one sync per k-step
    }

    // ---- epilogue: signs (+ rare exact repair), row/col counts ----
    if (tid < BM) { rowSum[tid] = 0; colSum[tid] = 0; }
    __syncthreads();

    bool diag = (bi == bj);
    int rcnt[2][2];  rcnt[0][0] = rcnt[0][1] = rcnt[1][0] = rcnt[1][1] = 0;
    int ccnt[16];
    #pragma unroll
    for (int q = 0; q < 16; q++) ccnt[q] = 0;

    int rbase = wm * 32 + (lane >> 2);
    int cbase = wn * 64 + (lane & 3) * 2;

    #pragma unroll
    for (int im = 0; im < 2; im++) {
        #pragma unroll
        for (int jn = 0; jn < 8; jn++) {
            #pragma unroll
            for (int e4 = 0; e4 < 4; e4++) {
                int h = e4 >> 1, e = e4 & 1;
                int gi = i0 + rbase + im * 16 + h * 8;
                int gj = j0 + cbase + jn * 8 + e;
                if (diag && gj <= gi) continue;
                float v = acc[im][jn][e4];
                int c;
                if (fabsf(v) >= TAU) c = (v >= 0.0f);
                else                 c = (exact_dot(X, gi, gj) >= 0.0f);
                rcnt[im][h] += c;
                ccnt[jn * 2 + e] += c;
            }
        }
    }
    #pragma unroll
    for (int im = 0; im < 2; im++)
        #pragma unroll
        for (int h = 0; h < 2; h++)
            atomicAdd(&rowSum[rbase + im * 16 + h * 8], rcnt[im][h]);
    #pragma unroll
    for (int jn = 0; jn < 8; jn++)
        #pragma unroll
        for (int e = 0; e < 2; e++)
            atomicAdd(&colSum[cbase + jn * 8 + e], ccnt[jn * 2 + e]);
    __syncthreads();

    if (tid < BM) {
        if (rowSum[tid]) atomicAdd(&g_counts[i0 + tid], rowSum[tid]);
        if (colSum[tid]) atomicAdd(&g_counts[j0 + tid], colSum[tid]);
    }
}

// ---------------------------------------------------------------------------
// 2) grid-wide argmin of counts via packed key atomicMin (first occurrence)
// ---------------------------------------------------------------------------
__global__ void argmin_kernel() {
    int i = blockIdx.x * blockDim.x + threadIdx.x;   // 4096 threads
    int key = g_counts[i] * 4096 + i;
    #pragma unroll
    for (int o = 16; o > 0; o >>= 1)
        key = min(key, __shfl_xor_sync(0xffffffffu, key, o));
    if ((threadIdx.x & 31) == 0) atomicMin(&g_best, key);
}

// ---------------------------------------------------------------------------
// 3) sim[seed][j] for all j + initial mask. warp per j, float4 loads.
// ---------------------------------------------------------------------------
__global__ void seedrow_kernel(const float* __restrict__ X,
                               const int* __restrict__ attn) {
    int gwarp = (blockIdx.x * blockDim.x + threadIdx.x) >> 5;
    int lane  = threadIdx.x & 31;
    if (gwarp >= NPTS) return;
    int seed = blend_seed(g_best, attn);
    const float4* xs = (const float4*)(X + (size_t)seed * DIM);
    const float4* xj = (const float4*)(X + (size_t)gwarp * DIM);
    float p = 0.0f;
    #pragma unroll
    for (int q = 0; q < 6; q++) {
        float4 u = xs[lane + 32 * q], w = xj[lane + 32 * q];
        p += u.x * w.x + u.y * w.y + u.z * w.z + u.w * w.w;
    }
    #pragma unroll
    for (int o = 16; o > 0; o >>= 1) p += __shfl_down_sync(0xffffffffu, p, o);
    if (lane == 0) {
        g_simseed[gwarp] = p;
        g_s[gwarp] = (p >= 0.0f) ? 1 : 0;
    }
}

// ---------------------------------------------------------------------------
// 4) top-100 via bitonic sort on packed 64-bit keys
// ---------------------------------------------------------------------------
__device__ __forceinline__ unsigned ford(float v) {   // monotonic float->uint
    unsigned u = __float_as_uint(v);
    return (u & 0x80000000u) ? ~u : (u | 0x80000000u);
}
__global__ void topk_kernel(const int* __restrict__ attn) {
    __shared__ unsigned long long sk[NPTS];
    int tid = threadIdx.x;   // 1024 threads
    int seed = blend_seed(g_best, attn);
    for (int i = tid; i < NPTS; i += 1024)
        sk[i] = ((unsigned long long)ford(g_simseed[i]) << 32)
              | (unsigned)(NPTS - 1 - i);
    __syncthreads();
    for (int k = 2; k <= NPTS; k <<= 1) {
        for (int j = k >> 1; j > 0; j >>= 1) {
            for (int i = tid; i < NPTS; i += 1024) {
                int ixj = i ^ j;
                if (ixj > i) {
                    unsigned long long k1 = sk[i], k2 = sk[ixj];
                    bool g = (k1 < k2);
                    bool dirDesc = ((i & k) == 0);
                    if (g == dirDesc) { sk[i] = k2; sk[ixj] = k1; }
                }
            }
            __syncthreads();
        }
    }
    unsigned long long k99 = sk[KTOP - 1];
    for (int i = tid; i < NPTS; i += 1024) {
        int s = g_s[i];
        if (i == seed) s = 1;
        unsigned long long ki = ((unsigned long long)ford(g_simseed[i]) << 32)
                              | (unsigned)(NPTS - 1 - i);
        g_s[i] = (ki >= k99) ? s : 0;
    }
}

// ---------------------------------------------------------------------------
// 5) sequential expansion, single warp, float4 loads, register accumulator.
// ---------------------------------------------------------------------------
__global__ void scan_kernel(const float* __restrict__ X) {
    __shared__ int list[KTOP + 32];
    int lane = threadIdx.x;   // 32 threads

    int cnt = 0;
    for (int c = 0; c < NPTS / 32; c++) {
        int idx = c * 32 + lane;
        int val = g_s[idx];
        unsigned m = __ballot_sync(0xffffffffu, val != 0);
        if (val) {
            int pos = cnt + __popc(m & ((1u << lane) - 1));
            if (pos < KTOP + 32) list[pos] = idx;
        }
        cnt += __popc(m);
    }
    int na = (cnt < KTOP + 32) ? cnt : (KTOP + 32);
    __syncwarp();

    float4 v4[6];
    #pragma unroll
    for (int q = 0; q < 6; q++) v4[q] = make_float4(0.f, 0.f, 0.f, 0.f);
    for (int l = 0; l < na; l++) {
        const float4* x = (const float4*)(X + (size_t)list[l] * DIM);
        #pragma unroll
        for (int q = 0; q < 6; q++) {
            float4 u = x[lane + 32 * q];
            v4[q].x += u.x; v4[q].y += u.y; v4[q].z += u.z; v4[q].w += u.w;
        }
    }

    for (int l = 0; l < na; l++) {
        int i = list[l];
        const float4* x = (const float4*)(X + (size_t)i * DIM);
        float4 xr[6];
        float dot = 0.0f;
        #pragma unroll
        for (int q = 0; q < 6; q++) {
            xr[q] = x[lane + 32 * q];
            dot += xr[q].x * v4[q].x + xr[q].y * v4[q].y
                 + xr[q].z * v4[q].z + xr[q].w * v4[q].w;
        }
        #pragma unroll
        for (int o = 16; o > 0; o >>= 1) dot += __shfl_xor_sync(0xffffffffu, dot, o);
        if (dot <= 0.0f) {                 // grows = (sum > 0) fails -> drop
            if (lane == 0) g_s[i] = 0;
            #pragma unroll
            for (int q = 0; q < 6; q++) {
                v4[q].x -= xr[q].x; v4[q].y -= xr[q].y;
                v4[q].z -= xr[q].z; v4[q].w -= xr[q].w;
            }
        }
    }
}

// ---------------------------------------------------------------------------
// 6) 8-connected components: in-place min-label propagation to fixpoint.
// ---------------------------------------------------------------------------
__global__ void cc_kernel(float* __restrict__ outp) {
    __shared__ int lab[66 * 66];
    __shared__ int changed;
    const int BIG = NPTS + 1;
    int tid = threadIdx.x;   // 1024 threads

    for (int p = tid; p < 66 * 66; p += 1024) lab[p] = BIG;
    __syncthreads();

    int fgp[4], pos[4];
    #pragma unroll
    for (int q = 0; q < 4; q++) {
        int p = tid + q * 1024;
        int r = p >> 6, c = p & 63;
        pos[q] = (r + 1) * 66 + (c + 1);
        fgp[q] = g_s[p];
        lab[pos[q]] = fgp[q] ? (p + 1) : BIG;
    }
    __syncthreads();

    while (true) {
        if (tid == 0) changed = 0;
        __syncthreads();
        int lc = 0;
        #pragma unroll
        for (int q = 0; q < 4; q++) {
            if (fgp[q]) {
                int pp = pos[q];
                int m = lab[pp];
                m = min(m, lab[pp - 67]); m = min(m, lab[pp - 66]); m = min(m, lab[pp - 65]);
                m = min(m, lab[pp - 1]);                            m = min(m, lab[pp + 1]);
                m = min(m, lab[pp + 65]); m = min(m, lab[pp + 66]); m = min(m, lab[pp + 67]);
                if (m < lab[pp]) { lab[pp] = m; lc = 1; }
            }
        }
        if (lc) changed = 1;
        __syncthreads();
        int done = !changed;
        __syncthreads();
        if (done) break;
    }

    #pragma unroll
    for (int q = 0; q < 4; q++) {
        int p = tid + q * 1024;
        outp[p] = fgp[q] ? (float)lab[pos[q]] : 0.0f;
    }
}

// ---------------------------------------------------------------------------
extern "C" void kernel_launch(void* const* d_in, const int* in_sizes, int n_in,
                              void* d_out, int out_size) {
    const float* X;
    const int*   attn;
    if (n_in >= 2 && in_sizes[0] == 2) {
        attn = (const int*)d_in[0];
        X    = (const float*)d_in[1];
    } else {
        X    = (const float*)d_in[0];
        attn = (const int*)d_in[1];
    }
    float* outp = (float*)d_out;

    convert_split<<<(NPTS * DIM / 4) / 256, 256>>>(X);
    count_mma<<<NT, 256>>>(X);
    argmin_kernel<<<16, 256>>>();
    seedrow_kernel<<<NPTS / 8, 256>>>(X, attn);
    topk_kernel<<<1, 1024>>>(attn);
    scan_kernel<<<1, 32>>>(X);
    cc_kernel<<<1, 1024>>>(outp);
}

// round 17
// speedup vs baseline: 2.6635x; 2.5452x over previous
#include <cuda_runtime.h>
#include <cuda_fp16.h>
#include <cstdint>
#include <limits.h>

#define NPTS 4096
#define DIM  768
#define WD   64
#define KTOP 100
#define NT   528
#define BM   128
#define PADK 24
#define TBA  (BM * PADK * 2)        // 6144 bytes per tile array
#define TAU  0.08f                  // ~10 sigma of the fp16 2-pass residual
#define RCAP (1 << 20)              // repair list capacity

// scratch (no allocations allowed)
__device__ int      g_counts[NPTS];
__device__ int      g_best;          // packed argmin key: count*4096 + idx
__device__ int      g_rep_n;         // repair list length
__device__ unsigned g_rep[RCAP];     // packed (gi<<12)|gj
__device__ float    g_simseed[NPTS];
__device__ int      g_s[NPTS];
__device__ __half   g_H[NPTS * DIM]; // fp16 hi (6.3MB)
__device__ __half   g_L[NPTS * DIM]; // fp16 lo (6.3MB)

// ---------------------------------------------------------------------------
__device__ __forceinline__ void ldsm_x4(uint32_t r[4], uint32_t addr) {
    asm volatile("ldmatrix.sync.aligned.m8n8.x4.shared.b16 {%0,%1,%2,%3}, [%4];"
                 : "=r"(r[0]), "=r"(r[1]), "=r"(r[2]), "=r"(r[3]) : "r"(addr));
}
__device__ __forceinline__ void mma_f16(float d[4], const uint32_t a[4],
                                        uint32_t b0, uint32_t b1) {
    asm volatile("mma.sync.aligned.m16n8k16.row.col.f32.f16.f16.f32 "
                 "{%0,%1,%2,%3},{%4,%5,%6,%7},{%8,%9},{%0,%1,%2,%3};"
                 : "+f"(d[0]), "+f"(d[1]), "+f"(d[2]), "+f"(d[3])
                 : "r"(a[0]), "r"(a[1]), "r"(a[2]), "r"(a[3]), "r"(b0), "r"(b1));
}
__device__ __forceinline__ float exact_dot(const float* __restrict__ X, int gi, int gj) {
    const float4* a = (const float4*)(X + (size_t)gi * DIM);
    const float4* b = (const float4*)(X + (size_t)gj * DIM);
    float s = 0.0f;
    #pragma unroll 4
    for (int d = 0; d < DIM / 4; d++) {
        float4 u = a[d], w = b[d];
        s += u.x * w.x + u.y * w.y + u.z * w.z + u.w * w.w;
    }
    return s;
}
__device__ __forceinline__ int blend_seed(int key, const int* __restrict__ attn) {
    int idx = key & 4095;
    int r = idx >> 6, c = idx & 63;
    int tr = r + attn[0];
    int tc = c + attn[1];
    int rr = tr >> 1; if (tr & 1) rr += (rr & 1);
    int cc = tc >> 1; if (tc & 1) cc += (cc & 1);
    return rr * WD + cc;
}

// ---------------------------------------------------------------------------
// 0) fp32 -> (fp16 hi, fp16 lo) split + global init (fused)
// ---------------------------------------------------------------------------
__global__ void convert_split(const float* __restrict__ X) {
    int i = blockIdx.x * blockDim.x + threadIdx.x;   // one float4 per thread
    if (i < NPTS) g_counts[i] = 1;                   // diagonal always >= 0
    if (i == 0) { g_best = INT_MAX; g_rep_n = 0; }
    float4 v = ((const float4*)X)[i];
    __half hx = __float2half_rn(v.x);
    __half hy = __float2half_rn(v.y);
    __half hz = __float2half_rn(v.z);
    __half hw = __float2half_rn(v.w);
    __half2* oh = (__half2*)g_H;
    __half2* ol = (__half2*)g_L;
    oh[2 * i + 0] = __half2(hx, hy);
    oh[2 * i + 1] = __half2(hz, hw);
    ol[2 * i + 0] = __floats2half2_rn(v.x - __half2float(hx),
                                      v.y - __half2float(hy));
    ol[2 * i + 1] = __floats2half2_rn(v.z - __half2float(hz),
                                      v.w - __half2float(hw));
}

// ---------------------------------------------------------------------------
// 1) triangular count-GEMM, fp16 2-pass HMMA: D = A_hi*B_hi + A_hi*B_lo.
//    Borderline |acc| < TAU pairs go to a global repair list (NO inline
//    exact dots -> no divergent serialization in the epilogue).
// ---------------------------------------------------------------------------
__global__ __launch_bounds__(256)
void count_mma(const float* __restrict__ X) {
    // decode triangular tile index t -> (bi, bj), bj >= bi
    int t = blockIdx.x;
    int bi = (int)((65.0 - sqrt(4225.0 - 8.0 * (double)t)) * 0.5);
    while (bi * (65 - bi) / 2 > t) bi--;
    while ((bi + 1) * (64 - bi) / 2 <= t) bi++;
    int bj = bi + (t - bi * (65 - bi) / 2);

    __shared__ __half Ah[2][BM * PADK];
    __shared__ __half Bh[2][BM * PADK];
    __shared__ __half Bl[2][BM * PADK];
    __shared__ int rowSum[BM];
    __shared__ int colSum[BM];

    int tid  = threadIdx.x;
    int warp = tid >> 5, lane = tid & 31;
    int wm = warp & 3;          // M group: rows wm*32..+31
    int wn = warp >> 2;         // N group: cols wn*64..+63
    int i0 = bi * BM, j0 = bj * BM;

    float acc[2][8][4];
    #pragma unroll
    for (int im = 0; im < 2; im++)
        #pragma unroll
        for (int jn = 0; jn < 8; jn++)
            #pragma unroll
            for (int e = 0; e < 4; e++) acc[im][jn][e] = 0.0f;

    // global load mapping: thread -> (row, 16B half) of the 128x16 stage
    int lrow = tid >> 1, lhalf = tid & 1;
    const uint4* gA  = (const uint4*)(g_H + (size_t)(i0 + lrow) * DIM);
    const uint4* gBh = (const uint4*)(g_H + (size_t)(j0 + lrow) * DIM);
    const uint4* gBl = (const uint4*)(g_L + (size_t)(j0 + lrow) * DIM);
    uint32_t stoff = (uint32_t)((lrow * PADK + lhalf * 8) * 2);

    // ldmatrix source lanes
    int rowA  = lane & 15;
    int koffA = (lane >> 4) * 8;
    int grp   = lane >> 3;
    int nB    = ((grp >> 1) * 8) + (lane & 7);
    int koffB = (grp & 1) * 8;

    uint32_t aAddr[2], bAddrH[4], bAddrL[4];
    {
        uint32_t ab  = (uint32_t)__cvta_generic_to_shared(&Ah[0][0]);
        uint32_t bbh = (uint32_t)__cvta_generic_to_shared(&Bh[0][0]);
        uint32_t bbl = (uint32_t)__cvta_generic_to_shared(&Bl[0][0]);
        #pragma unroll
        for (int im = 0; im < 2; im++)
            aAddr[im] = ab + ((wm * 32 + im * 16 + rowA) * PADK + koffA) * 2;
        #pragma unroll
        for (int jb = 0; jb < 4; jb++) {
            uint32_t off = ((wn * 64 + jb * 16 + nB) * PADK + koffB) * 2;
            bAddrH[jb] = bbh + off;
            bAddrL[jb] = bbl + off;
        }
    }
    const uint32_t bufBytes = TBA;

    uint4 ra, rbh, rbl;
    ra = gA[lhalf]; rbh = gBh[lhalf]; rbl = gBl[lhalf];
    *(uint4*)((char*)&Ah[0][0] + stoff) = ra;
    *(uint4*)((char*)&Bh[0][0] + stoff) = rbh;
    *(uint4*)((char*)&Bl[0][0] + stoff) = rbl;
    __syncthreads();

    for (int kt = 0; kt < 48; kt++) {
        int b = kt & 1;
        if (kt + 1 < 48) {          // prefetch next stage into registers
            int o = (kt + 1) * 2 + lhalf;
            ra = gA[o]; rbh = gBh[o]; rbl = gBl[o];
        }

        uint32_t ah[2][4], bh[4][4], bl[4][4];
        uint32_t bo = b * bufBytes;
        #pragma unroll
        for (int im = 0; im < 2; im++) ldsm_x4(ah[im], aAddr[im] + bo);
        #pragma unroll
        for (int jb = 0; jb < 4; jb++) {
            ldsm_x4(bh[jb], bAddrH[jb] + bo);
            ldsm_x4(bl[jb], bAddrL[jb] + bo);
        }

        if (kt + 1 < 48) {          // stores to the OTHER buffer
            *(uint4*)((char*)&Ah[b ^ 1][0] + stoff) = ra;
            *(uint4*)((char*)&Bh[b ^ 1][0] + stoff) = rbh;
            *(uint4*)((char*)&Bl[b ^ 1][0] + stoff) = rbl;
        }

        #pragma unroll
        for (int im = 0; im < 2; im++)
            #pragma unroll
            for (int jn = 0; jn < 8; jn++) {
                int jb = jn >> 1, o = (jn & 1) * 2;
                mma_f16(acc[im][jn], ah[im], bh[jb][o], bh[jb][o + 1]);
                mma_f16(acc[im][jn], ah[im], bl[jb][o], bl[jb][o + 1]);
            }

        __syncthreads();             // one sync per k-step
    }

    // ---- epilogue: confident signs counted; borderline -> repair list ----
    if (tid < BM) { rowSum[tid] = 0; colSum[tid] = 0; }
    __syncthreads();

    bool diag = (bi == bj);
    int rcnt[2][2];  rcnt[0][0] = rcnt[0][1] = rcnt[1][0] = rcnt[1][1] = 0;
    int ccnt[16];
    #pragma unroll
    for (int q = 0; q < 16; q++) ccnt[q] = 0;

    int rbase = wm * 32 + (lane >> 2);
    int cbase = wn * 64 + (lane & 3) * 2;

    #pragma unroll
    for (int im = 0; im < 2; im++) {
        #pragma unroll
        for (int jn = 0; jn < 8; jn++) {
            #pragma unroll
            for (int e4 = 0; e4 < 4; e4++) {
                int h = e4 >> 1, e = e4 & 1;
                int gi = i0 + rbase + im * 16 + h * 8;
                int gj = j0 + cbase + jn * 8 + e;
                if (diag && gj <= gi) continue;
                float v = acc[im][jn][e4];
                int c;
                if (fabsf(v) >= TAU) {
                    c = (v >= 0.0f);
                } else {
                    int slot = atomicAdd(&g_rep_n, 1);
                    if (slot < RCAP) {
                        g_rep[slot] = ((unsigned)gi << 12) | (unsigned)gj;
                        c = 0;                          // credited by repair kernel
                    } else {
                        c = (exact_dot(X, gi, gj) >= 0.0f);   // overflow fallback
                    }
                }
                rcnt[im][h] += c;
                ccnt[jn * 2 + e] += c;
            }
        }
    }
    #pragma unroll
    for (int im = 0; im < 2; im++)
        #pragma unroll
        for (int h = 0; h < 2; h++)
            atomicAdd(&rowSum[rbase + im * 16 + h * 8], rcnt[im][h]);
    #pragma unroll
    for (int jn = 0; jn < 8; jn++)
        #pragma unroll
        for (int e = 0; e < 2; e++)
            atomicAdd(&colSum[cbase + jn * 8 + e], ccnt[jn * 2 + e]);
    __syncthreads();

    if (tid < BM) {
        if (rowSum[tid]) atomicAdd(&g_counts[i0 + tid], rowSum[tid]);
        if (colSum[tid]) atomicAdd(&g_counts[j0 + tid], colSum[tid]);
    }
}

// ---------------------------------------------------------------------------
// 1b) batched repair: warp per borderline pair, coalesced fp32 warp-dot.
// ---------------------------------------------------------------------------
__global__ void repair_kernel(const float* __restrict__ X) {
    int gw   = (blockIdx.x * blockDim.x + threadIdx.x) >> 5;
    int lane = threadIdx.x & 31;
    int nw   = (gridDim.x * blockDim.x) >> 5;
    int n    = g_rep_n;
    if (n > RCAP) n = RCAP;

    for (int p = gw; p < n; p += nw) {
        unsigned pk = g_rep[p];
        int gi = (int)(pk >> 12), gj = (int)(pk & 4095u);
        const float4* a = (const float4*)(X + (size_t)gi * DIM);
        const float4* b = (const float4*)(X + (size_t)gj * DIM);
        float s = 0.0f;
        #pragma unroll
        for (int q = 0; q < 6; q++) {
            float4 u = a[lane + 32 * q], w = b[lane + 32 * q];
            s += u.x * w.x + u.y * w.y + u.z * w.z + u.w * w.w;
        }
        #pragma unroll
        for (int o = 16; o > 0; o >>= 1) s += __shfl_xor_sync(0xffffffffu, s, o);
        if (lane == 0 && s >= 0.0f) {
            atomicAdd(&g_counts[gi], 1);
            atomicAdd(&g_counts[gj], 1);
        }
    }
}

// ---------------------------------------------------------------------------
// 2) grid-wide argmin of counts via packed key atomicMin (first occurrence)
// ---------------------------------------------------------------------------
__global__ void argmin_kernel() {
    int i = blockIdx.x * blockDim.x + threadIdx.x;   // 4096 threads
    int key = g_counts[i] * 4096 + i;
    #pragma unroll
    for (int o = 16; o > 0; o >>= 1)
        key = min(key, __shfl_xor_sync(0xffffffffu, key, o));
    if ((threadIdx.x & 31) == 0) atomicMin(&g_best, key);
}

// ---------------------------------------------------------------------------
// 3) sim[seed][j] for all j + initial mask. warp per j, float4 loads.
// ---------------------------------------------------------------------------
__global__ void seedrow_kernel(const float* __restrict__ X,
                               const int* __restrict__ attn) {
    int gwarp = (blockIdx.x * blockDim.x + threadIdx.x) >> 5;
    int lane  = threadIdx.x & 31;
    if (gwarp >= NPTS) return;
    int seed = blend_seed(g_best, attn);
    const float4* xs = (const float4*)(X + (size_t)seed * DIM);
    const float4* xj = (const float4*)(X + (size_t)gwarp * DIM);
    float p = 0.0f;
    #pragma unroll
    for (int q = 0; q < 6; q++) {
        float4 u = xs[lane + 32 * q], w = xj[lane + 32 * q];
        p += u.x * w.x + u.y * w.y + u.z * w.z + u.w * w.w;
    }
    #pragma unroll
    for (int o = 16; o > 0; o >>= 1) p += __shfl_down_sync(0xffffffffu, p, o);
    if (lane == 0) {
        g_simseed[gwarp] = p;
        g_s[gwarp] = (p >= 0.0f) ? 1 : 0;
    }
}

// ---------------------------------------------------------------------------
// 4) top-100 via bitonic sort on packed 64-bit keys
// ---------------------------------------------------------------------------
__device__ __forceinline__ unsigned ford(float v) {   // monotonic float->uint
    unsigned u = __float_as_uint(v);
    return (u & 0x80000000u) ? ~u : (u | 0x80000000u);
}
__global__ void topk_kernel(const int* __restrict__ attn) {
    __shared__ unsigned long long sk[NPTS];
    int tid = threadIdx.x;   // 1024 threads
    int seed = blend_seed(g_best, attn);
    for (int i = tid; i < NPTS; i += 1024)
        sk[i] = ((unsigned long long)ford(g_simseed[i]) << 32)
              | (unsigned)(NPTS - 1 - i);
    __syncthreads();
    for (int k = 2; k <= NPTS; k <<= 1) {
        for (int j = k >> 1; j > 0; j >>= 1) {
            for (int i = tid; i < NPTS; i += 1024) {
                int ixj = i ^ j;
                if (ixj > i) {
                    unsigned long long k1 = sk[i], k2 = sk[ixj];
                    bool g = (k1 < k2);
                    bool dirDesc = ((i & k) == 0);
                    if (g == dirDesc) { sk[i] = k2; sk[ixj] = k1; }
                }
            }
            __syncthreads();
        }
    }
    unsigned long long k99 = sk[KTOP - 1];
    for (int i = tid; i < NPTS; i += 1024) {
        int s = g_s[i];
        if (i == seed) s = 1;
        unsigned long long ki = ((unsigned long long)ford(g_simseed[i]) << 32)
                              | (unsigned)(NPTS - 1 - i);
        g_s[i] = (ki >= k99) ? s : 0;
    }
}

// ---------------------------------------------------------------------------
// 5) sequential expansion, single warp, float4 loads, register accumulator.
// ---------------------------------------------------------------------------
__global__ void scan_kernel(const float* __restrict__ X) {
    __shared__ int list[KTOP + 32];
    int lane = threadIdx.x;   // 32 threads

    int cnt = 0;
    for (int c = 0; c < NPTS / 32; c++) {
        int idx = c * 32 + lane;
        int val = g_s[idx];
        unsigned m = __ballot_sync(0xffffffffu, val != 0);
        if (val) {
            int pos = cnt + __popc(m & ((1u << lane) - 1));
            if (pos < KTOP + 32) list[pos] = idx;
        }
        cnt += __popc(m);
    }
    int na = (cnt < KTOP + 32) ? cnt : (KTOP + 32);
    __syncwarp();

    float4 v4[6];
    #pragma unroll
    for (int q = 0; q < 6; q++) v4[q] = make_float4(0.f, 0.f, 0.f, 0.f);
    for (int l = 0; l < na; l++) {
        const float4* x = (const float4*)(X + (size_t)list[l] * DIM);
        #pragma unroll
        for (int q = 0; q < 6; q++) {
            float4 u = x[lane + 32 * q];
            v4[q].x += u.x; v4[q].y += u.y; v4[q].z += u.z; v4[q].w += u.w;
        }
    }

    for (int l = 0; l < na; l++) {
        int i = list[l];
        const float4* x = (const float4*)(X + (size_t)i * DIM);
        float4 xr[6];
        float dot = 0.0f;
        #pragma unroll
        for (int q = 0; q < 6; q++) {
            xr[q] = x[lane + 32 * q];
            dot += xr[q].x * v4[q].x + xr[q].y * v4[q].y
                 + xr[q].z * v4[q].z + xr[q].w * v4[q].w;
        }
        #pragma unroll
        for (int o = 16; o > 0; o >>= 1) dot += __shfl_xor_sync(0xffffffffu, dot, o);
        if (dot <= 0.0f) {                 // grows = (sum > 0) fails -> drop
            if (lane == 0) g_s[i] = 0;
            #pragma unroll
            for (int q = 0; q < 6; q++) {
                v4[q].x -= xr[q].x; v4[q].y -= xr[q].y;
                v4[q].z -= xr[q].z; v4[q].w -= xr[q].w;
            }
        }
    }
}

// ---------------------------------------------------------------------------
// 6) 8-connected components: in-place min-label propagation to fixpoint.
// ---------------------------------------------------------------------------
__global__ void cc_kernel(float* __restrict__ outp) {
    __shared__ int lab[66 * 66];
    __shared__ int changed;
    const int BIG = NPTS + 1;
    int tid = threadIdx.x;   // 1024 threads

    for (int p = tid; p < 66 * 66; p += 1024) lab[p] = BIG;
    __syncthreads();

    int fgp[4], pos[4];
    #pragma unroll
    for (int q = 0; q < 4; q++) {
        int p = tid + q * 1024;
        int r = p >> 6, c = p & 63;
        pos[q] = (r + 1) * 66 + (c + 1);
        fgp[q] = g_s[p];
        lab[pos[q]] = fgp[q] ? (p + 1) : BIG;
    }
    __syncthreads();

    while (true) {
        if (tid == 0) changed = 0;
        __syncthreads();
        int lc = 0;
        #pragma unroll
        for (int q = 0; q < 4; q++) {
            if (fgp[q]) {
                int pp = pos[q];
                int m = lab[pp];
                m = min(m, lab[pp - 67]); m = min(m, lab[pp - 66]); m = min(m, lab[pp - 65]);
                m = min(m, lab[pp - 1]);                            m = min(m, lab[pp + 1]);
                m = min(m, lab[pp + 65]); m = min(m, lab[pp + 66]); m = min(m, lab[pp + 67]);
                if (m < lab[pp]) { lab[pp] = m; lc = 1; }
            }
        }
        if (lc) changed = 1;
        __syncthreads();
        int done = !changed;
        __syncthreads();
        if (done) break;
    }

    #pragma unroll
    for (int q = 0; q < 4; q++) {
        int p = tid + q * 1024;
        outp[p] = fgp[q] ? (float)lab[pos[q]] : 0.0f;
    }
}

// ---------------------------------------------------------------------------
extern "C" void kernel_launch(void* const* d_in, const int* in_sizes, int n_in,
                              void* d_out, int out_size) {
    const float* X;
    const int*   attn;
    if (n_in >= 2 && in_sizes[0] == 2) {
        attn = (const int*)d_in[0];
        X    = (const float*)d_in[1];
    } else {
        X    = (const float*)d_in[0];
        attn = (const int*)d_in[1];
    }
    float* outp = (float*)d_out;

    convert_split<<<(NPTS * DIM / 4) / 256, 256>>>(X);
    count_mma<<<NT, 256>>>(X);
    repair_kernel<<<296, 256>>>(X);
    argmin_kernel<<<16, 256>>>();
    seedrow_kernel<<<NPTS / 8, 256>>>(X, attn);
    topk_kernel<<<1, 1024>>>(attn);
    scan_kernel<<<1, 32>>>(X);
    cc_kernel<<<1, 1024>>>(outp);
}